// round 9
// baseline (speedup 1.0000x reference)
#include <cuda_runtime.h>
#include <cuda_fp16.h>
#include <cstdint>
#include <math.h>

// Shapes (fixed)
constexpr int NROW = 128;
constexpr int DDIM = 512;
constexpr int CDIM = 8192;
constexpr int NQ   = 32768;

// ---------------- device scratch ----------------
__device__ __align__(16) float g_s1[(size_t)NROW * NQ];
__device__ __align__(16) float g_s2[(size_t)NROW * NQ];
__device__ __align__(16) unsigned short g_a1[NROW * DDIM];   // fp16 normalized new_embeds
__device__ __align__(16) unsigned short g_a2[NROW * CDIM];   // fp16 new_logits
__device__ int   g_qlab[NQ];
__device__ float g_part[256 * 8];     // per (row, half): m1,l1,m2,l2,sw,s1w,s2w,cnt

// ---------------- small helpers ----------------
__device__ __forceinline__ uint32_t smem_u32(const void* p) {
    uint32_t a;
    asm("{ .reg .u64 t; cvta.to.shared.u64 t, %1; cvt.u32.u64 %0, t; }" : "=r"(a) : "l"(p));
    return a;
}
__device__ __forceinline__ void ldm4(uint32_t* r, uint32_t addr) {
    asm volatile("ldmatrix.sync.aligned.m8n8.x4.shared.b16 {%0,%1,%2,%3}, [%4];"
                 : "=r"(r[0]), "=r"(r[1]), "=r"(r[2]), "=r"(r[3]) : "r"(addr));
}
__device__ __forceinline__ void mma_f16(float* d, const uint32_t* a, const uint32_t* b) {
    asm volatile(
        "mma.sync.aligned.m16n8k16.row.col.f32.f16.f16.f32 "
        "{%0,%1,%2,%3}, {%4,%5,%6,%7}, {%8,%9}, {%0,%1,%2,%3};"
        : "+f"(d[0]), "+f"(d[1]), "+f"(d[2]), "+f"(d[3])
        : "r"(a[0]), "r"(a[1]), "r"(a[2]), "r"(a[3]), "r"(b[0]), "r"(b[1]));
}
#define CP16(saddr, gptr) \
    asm volatile("cp.async.ca.shared.global [%0], [%1], 16;" :: "r"(saddr), "l"(gptr))
#define CP_COMMIT()  asm volatile("cp.async.commit_group;" ::: "memory")
#define CP_WAIT(N)   asm volatile("cp.async.wait_group %0;" :: "n"(N) : "memory")
#define BAR_SYNC(id)   asm volatile("bar.sync %0, %1;"   :: "r"(id), "r"(384) : "memory")
#define BAR_ARRIVE(id) asm volatile("bar.arrive %0, %1;" :: "r"(id), "r"(384) : "memory")

// ---------------- kernel: normalize new_embeds -> fp16 ----------------
__global__ void normalize_half(const float* __restrict__ x) {
    int i = blockIdx.x, tid = threadIdx.x;           // 128 threads
    const float* xr = x + (size_t)i * DDIM;
    float s = 0.f;
    for (int d = tid; d < DDIM; d += 128) { float v = xr[d]; s += v * v; }
    for (int o = 16; o; o >>= 1) s += __shfl_down_sync(0xffffffffu, s, o);
    __shared__ float sh[4];
    if ((tid & 31) == 0) sh[tid >> 5] = s;
    __syncthreads();
    __shared__ float invs;
    if (tid == 0) invs = 1.0f / fmaxf(sqrtf(sh[0] + sh[1] + sh[2] + sh[3]), 1e-12f);
    __syncthreads();
    float iv = invs;
    for (int d = tid; d < DDIM; d += 128)
        g_a1[i * DDIM + d] = __half_as_ushort(__float2half_rn(xr[d] * iv));
}

// ---------------- kernel: new_logits -> fp16 ----------------
__global__ void half_logits(const float* __restrict__ x) {
    int idx = (blockIdx.x * blockDim.x + threadIdx.x) * 4;   // over 128*8192
    float4 v = *(const float4*)(x + idx);
    __half2 h0 = __floats2half2_rn(v.x, v.y);
    __half2 h1 = __floats2half2_rn(v.z, v.w);
    uint2 p; p.x = *(uint32_t*)&h0; p.y = *(uint32_t*)&h1;
    *(uint2*)(g_a2 + idx) = p;
}

// ---------------- kernel: updated queue labels ----------------
__global__ void build_qlab(const int* __restrict__ ql, const int* __restrict__ labels,
                           const int* __restrict__ hdrp) {
    int j = blockIdx.x * blockDim.x + threadIdx.x;
    int hdr = *hdrp;
    int r = (j - hdr) & (NQ - 1);
    g_qlab[j] = (r < NROW) ? labels[r] : ql[j];
}

// ---------------- warp-specialized fp16 GEMM ----------------
// 384 threads: warps 0-7 = consumers (MMA only), warps 8-11 = producers
// (cp.async A fp16, cp.async B fp32 -> staging, convert -> fp16 tile, STS).
// 4-stage ring, named barriers: READY(s)=1+s (prod arrive / cons sync),
// FREE(s)=5+s (cons arrive / prod sync). CTA tile 128x128, BK=32.
constexpr int BPAD  = 80;                  // fp16 tile row stride (conflict-free ldmatrix)
constexpr int FSTR  = 144;                 // fp32 staging row stride (128B data + 16B pad)
constexpr int SZ_A  = 128 * BPAD;          // 10240
constexpr int SZ_B  = 128 * BPAD;          // 10240
constexpr int SZ_F  = 128 * FSTR;          // 18432
constexpr int NSTG  = 4;
constexpr int O_AT  = 0;                   // A tiles   [4 x 10240]
constexpr int O_BT  = NSTG * SZ_A;         // 40960, B tiles [4 x 10240]
constexpr int O_FS  = O_BT + NSTG * SZ_B;  // 81920, fp32 staging [4 x 18432]
constexpr int GEMM_SMEM = O_FS + NSTG * SZ_F;   // 155648 (152KB)

__global__ __launch_bounds__(384, 1) void gemm_mma(
    const unsigned short* __restrict__ A,    // [128 x K] fp16
    const float* __restrict__ Bq,            // [NQ x K]
    const float* __restrict__ Bold,          // [128 x K]
    const int* __restrict__ hdrp,
    float* __restrict__ out,                 // [128 x NQ]
    int K)
{
    extern __shared__ char smem[];
    const uint32_t sb = smem_u32(smem);
    const int tid = threadIdx.x, lane = tid & 31, wid = tid >> 5;
    const int n0 = blockIdx.x * 128;
    const int nch = K >> 5;

    if (wid < 8) {
        // ================= consumers: MMA only =================
        const int wm = wid >> 1, wn = wid & 1;
        const int g = lane >> 3, lr = lane & 7;
        const uint32_t aRowOff = (uint32_t)(wm * 32 + (g & 1) * 8 + lr) * BPAD + (g >> 1) * 16;
        const uint32_t bRowOff = (uint32_t)(wn * 64 + (g >> 1) * 8 + lr) * BPAD + (g & 1) * 16;

        float acc[2][8][4];
#pragma unroll
        for (int mt = 0; mt < 2; mt++)
#pragma unroll
            for (int nt = 0; nt < 8; nt++)
#pragma unroll
                for (int u = 0; u < 4; u++) acc[mt][nt][u] = 0.f;

        for (int c = 0; c < nch; c++) {
            const int st = c & 3;
            BAR_SYNC(1 + st);
            const uint32_t bA = sb + O_AT + st * SZ_A + aRowOff;
            const uint32_t bB = sb + O_BT + st * SZ_B + bRowOff;
#pragma unroll
            for (int ks = 0; ks < 2; ks++) {
                uint32_t a[2][4], b[4][4];
                ldm4(a[0], bA + ks * 32);
                ldm4(a[1], bA + 16 * BPAD + ks * 32);
#pragma unroll
                for (int p = 0; p < 4; p++) ldm4(b[p], bB + p * 16 * BPAD + ks * 32);
#pragma unroll
                for (int mt = 0; mt < 2; mt++)
#pragma unroll
                    for (int nt = 0; nt < 8; nt++)
                        mma_f16(acc[mt][nt], a[mt], &b[nt >> 1][(nt & 1) * 2]);
            }
            BAR_ARRIVE(5 + st);
        }

        // epilogue
        const int qr = lane >> 2, qc = (lane & 3) * 2;
#pragma unroll
        for (int mt = 0; mt < 2; mt++) {
            const int row = wm * 32 + mt * 16 + qr;
#pragma unroll
            for (int nt = 0; nt < 8; nt++) {
                const int col = n0 + wn * 64 + nt * 8 + qc;
                float2 v0; v0.x = acc[mt][nt][0]; v0.y = acc[mt][nt][1];
                float2 v1; v1.x = acc[mt][nt][2]; v1.y = acc[mt][nt][3];
                *(float2*)(out + (size_t)row * NQ + col) = v0;
                *(float2*)(out + (size_t)(row + 8) * NQ + col) = v1;
            }
        }
    } else {
        // ================= producers: load + convert =================
        const int pt = tid - 256;                    // 0..127, one B/A row each
        const int hdr = *hdrp;
        const int jq = n0 + pt;
        const int rr = (jq - hdr) & (NQ - 1);
        const char* gB = (const char*)((rr < NROW) ? (Bold + (size_t)rr * K)
                                                   : (Bq + (size_t)jq * K));
        const char* gA = (const char*)A + (size_t)pt * K * 2;

        auto cpStage = [&](int f) {
            const int s = f & 3;
            // A: 64B of fp16 straight into the tile
            uint32_t dA = sb + O_AT + s * SZ_A + pt * BPAD;
            const char* srcA = gA + (size_t)f * 64;
#pragma unroll
            for (int i = 0; i < 4; i++) CP16(dA + 16 * i, srcA + 16 * i);
            // B: 128B of fp32 into staging
            uint32_t dB = sb + O_FS + s * SZ_F + pt * FSTR;
            const char* srcB = gB + (size_t)f * 128;
#pragma unroll
            for (int i = 0; i < 8; i++) CP16(dB + 16 * i, srcB + 16 * i);
            CP_COMMIT();
        };

        auto convertB = [&](int s) {
            const char* base = smem + O_FS + s * SZ_F + pt * FSTR;
            char* dh = smem + O_BT + s * SZ_B + pt * BPAD;
#pragma unroll
            for (int h = 0; h < 4; h++) {
                float4 x = *(const float4*)(base + 32 * h);
                float4 y = *(const float4*)(base + 32 * h + 16);
                __half2 a0 = __floats2half2_rn(x.x, x.y);
                __half2 a1 = __floats2half2_rn(x.z, x.w);
                __half2 a2 = __floats2half2_rn(y.x, y.y);
                __half2 a3 = __floats2half2_rn(y.z, y.w);
                uint4 p;
                p.x = *(uint32_t*)&a0; p.y = *(uint32_t*)&a1;
                p.z = *(uint32_t*)&a2; p.w = *(uint32_t*)&a3;
                *(uint4*)(dh + 16 * h) = p;
            }
        };

        // prologue: fill stages 0,1,2 (nch >= 16 always)
        for (int f = 0; f < 3; f++) cpStage(f);

        for (int c = 0; c < nch; c++) {
            const int f = c + 3;
            if (f < nch) {
                if (f >= 4) BAR_SYNC(5 + (f & 3));   // wait stage free (chunk f-4 done)
                cpStage(f);
                CP_WAIT(3);                          // group c retired -> stage c landed
            } else {
                CP_WAIT(0);                          // tail: drain everything
            }
            convertB(c & 3);
            BAR_ARRIVE(1 + (c & 3));                 // publish chunk c
        }
    }
}

// ---------------- per-row reduction: 2 blocks per row (half-Q each) ----------------
__global__ __launch_bounds__(256) void row_reduce(
    const float* __restrict__ old_embeds, const float* __restrict__ feat_queue,
    const int* __restrict__ labels, const int* __restrict__ hdrp)
{
    const int i = blockIdx.x >> 1, half = blockIdx.x & 1, tid = threadIdx.x;
    const int lbl = labels[i];
    const int hdr = *hdrp;
    const int j0 = half * (NQ / 2);
    const float4* s1r = (const float4*)(g_s1 + (size_t)i * NQ + j0);
    const float4* s2r = (const float4*)(g_s2 + (size_t)i * NQ + j0);
    const int4*   ql4 = (const int4*)(g_qlab + j0);
    const float* oei = old_embeds + (size_t)i * DDIM;
    constexpr int NV = (NQ / 2) / 4;

    float m1 = -INFINITY, m2 = -INFINITY;
    for (int v = tid; v < NV; v += 256) {
        float4 a = s1r[v], b = s2r[v];
        m1 = fmaxf(fmaxf(fmaxf(m1, a.x), fmaxf(a.y, a.z)), a.w);
        m2 = fmaxf(fmaxf(fmaxf(m2, b.x), fmaxf(b.y, b.z)), b.w);
    }
    for (int o = 16; o; o >>= 1) {
        m1 = fmaxf(m1, __shfl_xor_sync(0xffffffffu, m1, o));
        m2 = fmaxf(m2, __shfl_xor_sync(0xffffffffu, m2, o));
    }
    __shared__ float shm1[8], shm2[8];
    if ((tid & 31) == 0) { shm1[tid >> 5] = m1; shm2[tid >> 5] = m2; }
    __syncthreads();
    float M1 = shm1[0], M2 = shm2[0];
    for (int w = 1; w < 8; w++) { M1 = fmaxf(M1, shm1[w]); M2 = fmaxf(M2, shm2[w]); }

    float l1 = 0.f, l2 = 0.f, sw = 0.f, s1w = 0.f, s2w = 0.f, cnt = 0.f;
    for (int v = tid; v < NV; v += 256) {
        float4 a = s1r[v], b = s2r[v];
        l1 += __expf(a.x - M1) + __expf(a.y - M1) + __expf(a.z - M1) + __expf(a.w - M1);
        l2 += __expf(b.x - M2) + __expf(b.y - M2) + __expf(b.z - M2) + __expf(b.w - M2);
        int4 q = ql4[v];
        if (q.x == lbl || q.y == lbl || q.z == lbl || q.w == lbl) {
            const float va[4] = {a.x, a.y, a.z, a.w};
            const float vb[4] = {b.x, b.y, b.z, b.w};
            const int   qq[4] = {q.x, q.y, q.z, q.w};
#pragma unroll
            for (int e = 0; e < 4; e++) {
                if (qq[e] != lbl) continue;
                int jj = j0 + v * 4 + e;
                int r = (jj - hdr) & (NQ - 1);
                const float* frow = (r < NROW) ? (old_embeds + (size_t)r * DDIM)
                                               : (feat_queue + (size_t)jj * DDIM);
                float dot = 0.f;
#pragma unroll 8
                for (int d = 0; d < DDIM; d++) dot = fmaf(oei[d], frow[d], dot);
                float w = 0.5f * (dot + 1.0f);
                sw += w; s1w += w * va[e]; s2w += w * vb[e]; cnt += 1.f;
            }
        }
    }
    for (int o = 16; o; o >>= 1) {
        l1  += __shfl_down_sync(0xffffffffu, l1, o);
        l2  += __shfl_down_sync(0xffffffffu, l2, o);
        sw  += __shfl_down_sync(0xffffffffu, sw, o);
        s1w += __shfl_down_sync(0xffffffffu, s1w, o);
        s2w += __shfl_down_sync(0xffffffffu, s2w, o);
        cnt += __shfl_down_sync(0xffffffffu, cnt, o);
    }
    __shared__ float shl1[8], shl2[8], shsw[8], shs1[8], shs2[8], shc[8];
    if ((tid & 31) == 0) {
        int w = tid >> 5;
        shl1[w] = l1; shl2[w] = l2; shsw[w] = sw; shs1[w] = s1w; shs2[w] = s2w; shc[w] = cnt;
    }
    __syncthreads();
    if (tid == 0) {
        float L1 = 0, L2 = 0, SW = 0, S1 = 0, S2 = 0, CN = 0;
        for (int w = 0; w < 8; w++) {
            L1 += shl1[w]; L2 += shl2[w]; SW += shsw[w];
            S1 += shs1[w]; S2 += shs2[w]; CN += shc[w];
        }
        float* p = g_part + blockIdx.x * 8;
        p[0] = M1; p[1] = L1; p[2] = M2; p[3] = L2;
        p[4] = SW; p[5] = S1; p[6] = S2; p[7] = CN;
    }
}

// ---------------- finalize ----------------
__global__ void finalize(float* __restrict__ out) {
    int tid = threadIdx.x;   // 128 threads, one row each
    const float* pa = g_part + (2 * tid) * 8;
    const float* pb = g_part + (2 * tid + 1) * 8;
    float M1 = fmaxf(pa[0], pb[0]);
    float L1 = pa[1] * __expf(pa[0] - M1) + pb[1] * __expf(pb[0] - M1);
    float M2 = fmaxf(pa[2], pb[2]);
    float L2 = pa[3] * __expf(pa[2] - M2) + pb[3] * __expf(pb[2] - M2);
    float SW = pa[4] + pb[4];
    float S1 = pa[5] + pb[5];
    float S2 = pa[6] + pb[6];
    float CN = pa[7] + pb[7];
    float lse1 = M1 + logf(L1);
    float lse2 = M2 + logf(L2);
    float ic = 1.0f / CN;
    float t1 = (S1 - lse1 * SW) * ic;
    float t2 = (S2 - lse2 * SW) * ic;
    for (int o = 16; o; o >>= 1) {
        t1 += __shfl_down_sync(0xffffffffu, t1, o);
        t2 += __shfl_down_sync(0xffffffffu, t2, o);
    }
    __shared__ float sh1[4], sh2[4];
    if ((tid & 31) == 0) { sh1[tid >> 5] = t1; sh2[tid >> 5] = t2; }
    __syncthreads();
    if (tid == 0) {
        out[0] = -(sh1[0] + sh1[1] + sh1[2] + sh1[3]) / (float)NROW;
        out[1] = -(sh2[0] + sh2[1] + sh2[2] + sh2[3]) / (float)NROW;
    }
}

// ---------------- launch ----------------
extern "C" void kernel_launch(void* const* d_in, const int* in_sizes, int n_in,
                              void* d_out, int out_size) {
    const float* old_embeds   = (const float*)d_in[0];
    const float* old_logits   = (const float*)d_in[1];
    const float* new_embeds   = (const float*)d_in[2];
    const float* new_logits   = (const float*)d_in[3];
    const int*   labels       = (const int*)d_in[4];
    const float* feat_queue   = (const float*)d_in[5];
    const float* logit_queue  = (const float*)d_in[6];
    const int*   queue_labels = (const int*)d_in[7];
    const int*   header       = (const int*)d_in[8];
    float* out = (float*)d_out;

    unsigned short *p_a1, *p_a2;
    float *p_s1, *p_s2;
    cudaGetSymbolAddress((void**)&p_a1, g_a1);
    cudaGetSymbolAddress((void**)&p_a2, g_a2);
    cudaGetSymbolAddress((void**)&p_s1, g_s1);
    cudaGetSymbolAddress((void**)&p_s2, g_s2);

    cudaFuncSetAttribute(gemm_mma, cudaFuncAttributeMaxDynamicSharedMemorySize, GEMM_SMEM);

    normalize_half<<<NROW, 128>>>(new_embeds);
    half_logits<<<(NROW * CDIM) / (256 * 4), 256>>>(new_logits);
    build_qlab<<<NQ / 256, 256>>>(queue_labels, labels, header);

    gemm_mma<<<NQ / 128, 384, GEMM_SMEM>>>(p_a1, feat_queue, old_embeds,
                                           header, p_s1, DDIM);
    gemm_mma<<<NQ / 128, 384, GEMM_SMEM>>>(p_a2, logit_queue, old_logits,
                                           header, p_s2, CDIM);

    row_reduce<<<2 * NROW, 256>>>(old_embeds, feat_queue, labels, header);
    finalize<<<1, 128>>>(out);
}

// round 10
// speedup vs baseline: 1.2032x; 1.2032x over previous
#include <cuda_runtime.h>
#include <cuda_fp16.h>
#include <cstdint>
#include <math.h>

// Shapes (fixed)
constexpr int NROW = 128;
constexpr int DDIM = 512;
constexpr int CDIM = 8192;
constexpr int NQ   = 32768;

// ---------------- device scratch ----------------
__device__ __align__(16) float g_s1[(size_t)NROW * NQ];
__device__ __align__(16) float g_s2[(size_t)NROW * NQ];
__device__ __align__(16) unsigned short g_a1[NROW * DDIM];   // fp16 normalized new_embeds
__device__ __align__(16) unsigned short g_a2[NROW * CDIM];   // fp16 new_logits
__device__ int   g_qlab[NQ];
__device__ float g_part[256 * 8];     // per (row, half): m1,l1,m2,l2,sw,s1w,s2w,cnt

// ---------------- small helpers ----------------
__device__ __forceinline__ uint32_t smem_u32(const void* p) {
    uint32_t a;
    asm("{ .reg .u64 t; cvta.to.shared.u64 t, %1; cvt.u32.u64 %0, t; }" : "=r"(a) : "l"(p));
    return a;
}
__device__ __forceinline__ void ldm4(uint32_t* r, uint32_t addr) {
    asm volatile("ldmatrix.sync.aligned.m8n8.x4.shared.b16 {%0,%1,%2,%3}, [%4];"
                 : "=r"(r[0]), "=r"(r[1]), "=r"(r[2]), "=r"(r[3]) : "r"(addr));
}
__device__ __forceinline__ void mma_f16(float* d, const uint32_t* a, const uint32_t* b) {
    asm volatile(
        "mma.sync.aligned.m16n8k16.row.col.f32.f16.f16.f32 "
        "{%0,%1,%2,%3}, {%4,%5,%6,%7}, {%8,%9}, {%0,%1,%2,%3};"
        : "+f"(d[0]), "+f"(d[1]), "+f"(d[2]), "+f"(d[3])
        : "r"(a[0]), "r"(a[1]), "r"(a[2]), "r"(a[3]), "r"(b[0]), "r"(b[1]));
}
#define CP16(saddr, gptr) \
    asm volatile("cp.async.ca.shared.global [%0], [%1], 16;" :: "r"(saddr), "l"(gptr))
#define CP_COMMIT() asm volatile("cp.async.commit_group;" ::: "memory")
#define CP_WAIT0()  asm volatile("cp.async.wait_group 0;" ::: "memory")

// ---------------- kernel: normalize new_embeds -> fp16 ----------------
__global__ void normalize_half(const float* __restrict__ x) {
    int i = blockIdx.x, tid = threadIdx.x;           // 128 threads
    const float* xr = x + (size_t)i * DDIM;
    float s = 0.f;
    for (int d = tid; d < DDIM; d += 128) { float v = xr[d]; s += v * v; }
    for (int o = 16; o; o >>= 1) s += __shfl_down_sync(0xffffffffu, s, o);
    __shared__ float sh[4];
    if ((tid & 31) == 0) sh[tid >> 5] = s;
    __syncthreads();
    __shared__ float invs;
    if (tid == 0) invs = 1.0f / fmaxf(sqrtf(sh[0] + sh[1] + sh[2] + sh[3]), 1e-12f);
    __syncthreads();
    float iv = invs;
    for (int d = tid; d < DDIM; d += 128)
        g_a1[i * DDIM + d] = __half_as_ushort(__float2half_rn(xr[d] * iv));
}

// ---------------- kernel: new_logits -> fp16 ----------------
__global__ void half_logits(const float* __restrict__ x) {
    int idx = (blockIdx.x * blockDim.x + threadIdx.x) * 4;   // over 128*8192
    float4 v = *(const float4*)(x + idx);
    __half2 h0 = __floats2half2_rn(v.x, v.y);
    __half2 h1 = __floats2half2_rn(v.z, v.w);
    uint2 p; p.x = *(uint32_t*)&h0; p.y = *(uint32_t*)&h1;
    *(uint2*)(g_a2 + idx) = p;
}

// ---------------- kernel: updated queue labels ----------------
__global__ void build_qlab(const int* __restrict__ ql, const int* __restrict__ labels,
                           const int* __restrict__ hdrp) {
    int j = blockIdx.x * blockDim.x + threadIdx.x;
    int hdr = *hdrp;
    int r = (j - hdr) & (NQ - 1);
    g_qlab[j] = (r < NROW) ? labels[r] : ql[j];
}

// ---------------- mma.sync fp16 GEMM, BK=64, interleaved producer halves ----------------
// D = A_fp16 @ B_fp16^T; CTA tile 128x128, BK=64; 8 warps (4M x 2N), warp tile 32x64.
// Per chunk: [cpA(c+1) + loadB.h0(c+1)] -> compute.h0(c) -> [storeB.h0 + loadB.h1]
//            -> compute.h1(c) -> [storeB.h1] -> wait+barrier.   One barrier per 64 K.
constexpr int BPAD = 144;                // row stride: 128B data + 16B pad (conflict-free)
constexpr int SZ_T = 128 * BPAD;         // 18432 per tile
constexpr int O_A  = 0;
constexpr int O_B  = SZ_T;               // 18432
constexpr int STG  = 2 * SZ_T;           // 36864 per stage
constexpr int GEMM_SMEM = 2 * STG;       // 73728 -> 2 CTAs/SM

__global__ __launch_bounds__(256, 2) void gemm_mma(
    const unsigned short* __restrict__ A,    // [128 x K] fp16
    const float* __restrict__ Bq,            // [NQ x K]
    const float* __restrict__ Bold,          // [128 x K]
    const int* __restrict__ hdrp,
    float* __restrict__ out,                 // [128 x NQ]
    int K)
{
    extern __shared__ char smem[];
    const uint32_t sb = smem_u32(smem);
    const int tid = threadIdx.x, lane = tid & 31, wid = tid >> 5;
    const int wm = wid >> 1, wn = wid & 1;
    const int n0 = blockIdx.x * 128;
    const int nchunks = K >> 6;

    // B gmem row with circular-queue redirect; 2 threads per row, fp32 cols [seg*32, seg*32+32)
    const int rb = tid >> 1, seg = tid & 1;
    const int hdr = *hdrp;
    const int j = n0 + rb;
    const int r = (j - hdr) & (NQ - 1);
    const float* gB = ((r < NROW) ? (Bold + (size_t)r * K) : (Bq + (size_t)j * K)) + seg * 32;

    // A: 2 threads per row, 64B each (row = 128B of fp16 per chunk)
    const int arow = tid >> 1;
    const int acol = (tid & 1) * 64;
    const char* gA = (const char*)A + (size_t)arow * K * 2 + acol;
    const uint32_t sA = sb + O_A + arow * BPAD + acol;

    // ldmatrix lane addressing
    const int g = lane >> 3, lr = lane & 7;
    const uint32_t aRowOff = (uint32_t)(wm * 32 + (g & 1) * 8 + lr) * BPAD + (g >> 1) * 16;
    const uint32_t bRowOff = (uint32_t)(wn * 64 + (g >> 1) * 8 + lr) * BPAD + (g & 1) * 16;

    float acc[2][8][4];
#pragma unroll
    for (int mt = 0; mt < 2; mt++)
#pragma unroll
        for (int nt = 0; nt < 8; nt++)
#pragma unroll
            for (int u = 0; u < 4; u++) acc[mt][nt][u] = 0.f;

    auto cpA = [&](int c, int st) {
        const char* s0 = gA + (size_t)c * 128;
        uint32_t d0 = sA + st * STG;
#pragma unroll
        for (int i = 0; i < 4; i++) CP16(d0 + 16 * i, s0 + 16 * i);
    };

    float4 f0, f1, f2, f3;                         // B staging (16 fp32 = one half)
    auto loadB = [&](int c, int h) {
        const float4* p = (const float4*)(gB + (size_t)c * 64 + h * 16);
        f0 = __ldg(p); f1 = __ldg(p + 1); f2 = __ldg(p + 2); f3 = __ldg(p + 3);
    };
    auto storeB = [&](int st, int h) {
        __half2 h0 = __floats2half2_rn(f0.x, f0.y);
        __half2 h1 = __floats2half2_rn(f0.z, f0.w);
        __half2 h2 = __floats2half2_rn(f1.x, f1.y);
        __half2 h3 = __floats2half2_rn(f1.z, f1.w);
        __half2 h4 = __floats2half2_rn(f2.x, f2.y);
        __half2 h5 = __floats2half2_rn(f2.z, f2.w);
        __half2 h6 = __floats2half2_rn(f3.x, f3.y);
        __half2 h7 = __floats2half2_rn(f3.z, f3.w);
        uint4 p0, p1;
        p0.x = *(uint32_t*)&h0; p0.y = *(uint32_t*)&h1;
        p0.z = *(uint32_t*)&h2; p0.w = *(uint32_t*)&h3;
        p1.x = *(uint32_t*)&h4; p1.y = *(uint32_t*)&h5;
        p1.z = *(uint32_t*)&h6; p1.w = *(uint32_t*)&h7;
        char* d = smem + st * STG + O_B + rb * BPAD + seg * 64 + h * 32;
        *(uint4*)d = p0;
        *(uint4*)(d + 16) = p1;
    };

    // compute half h of chunk in stage st: ks pair {2h, 2h+1}
    auto computeH = [&](int st, int h) {
        const uint32_t bA = sb + st * STG + O_A + aRowOff + h * 64;
        const uint32_t bB = sb + st * STG + O_B + bRowOff + h * 64;
#pragma unroll
        for (int ks = 0; ks < 2; ks++) {
            uint32_t a[2][4], b[4][4];
            ldm4(a[0], bA + ks * 32);
            ldm4(a[1], bA + 16 * BPAD + ks * 32);
#pragma unroll
            for (int p = 0; p < 4; p++) ldm4(b[p], bB + p * 16 * BPAD + ks * 32);
#pragma unroll
            for (int mt = 0; mt < 2; mt++)
#pragma unroll
                for (int nt = 0; nt < 8; nt++)
                    mma_f16(acc[mt][nt], a[mt], &b[nt >> 1][(nt & 1) * 2]);
        }
    };

    // ---- prologue: chunk 0 ----
    cpA(0, 0);
    CP_COMMIT();
    loadB(0, 0);
    storeB(0, 0);
    loadB(0, 1);
    storeB(0, 1);
    CP_WAIT0();
    __syncthreads();

    // ---- main loop: one barrier per 64-K chunk; producer work interleaved ----
    for (int c = 0; c < nchunks; c++) {
        const int st = c & 1;
        const bool more = (c + 1 < nchunks);
        if (more) {
            cpA(c + 1, st ^ 1);
            CP_COMMIT();
            loadB(c + 1, 0);           // LDG early, hidden under compute h0
        }
        computeH(st, 0);
        if (more) {
            storeB(st ^ 1, 0);         // convert+STS overlapped with compute h1's MMA drain
            loadB(c + 1, 1);
        }
        computeH(st, 1);
        if (more) storeB(st ^ 1, 1);
        CP_WAIT0();
        __syncthreads();
    }

    // ---- epilogue ----
    const int qr = lane >> 2, qc = (lane & 3) * 2;
#pragma unroll
    for (int mt = 0; mt < 2; mt++) {
        const int row = wm * 32 + mt * 16 + qr;
#pragma unroll
        for (int nt = 0; nt < 8; nt++) {
            const int col = n0 + wn * 64 + nt * 8 + qc;
            float2 v0; v0.x = acc[mt][nt][0]; v0.y = acc[mt][nt][1];
            float2 v1; v1.x = acc[mt][nt][2]; v1.y = acc[mt][nt][3];
            *(float2*)(out + (size_t)row * NQ + col) = v0;
            *(float2*)(out + (size_t)(row + 8) * NQ + col) = v1;
        }
    }
}

// ---------------- per-row reduction: 2 blocks per row (half-Q each) ----------------
__global__ __launch_bounds__(256) void row_reduce(
    const float* __restrict__ old_embeds, const float* __restrict__ feat_queue,
    const int* __restrict__ labels, const int* __restrict__ hdrp)
{
    const int i = blockIdx.x >> 1, half = blockIdx.x & 1, tid = threadIdx.x;
    const int lbl = labels[i];
    const int hdr = *hdrp;
    const int j0 = half * (NQ / 2);
    const float4* s1r = (const float4*)(g_s1 + (size_t)i * NQ + j0);
    const float4* s2r = (const float4*)(g_s2 + (size_t)i * NQ + j0);
    const int4*   ql4 = (const int4*)(g_qlab + j0);
    const float* oei = old_embeds + (size_t)i * DDIM;
    constexpr int NV = (NQ / 2) / 4;

    float m1 = -INFINITY, m2 = -INFINITY;
    for (int v = tid; v < NV; v += 256) {
        float4 a = s1r[v], b = s2r[v];
        m1 = fmaxf(fmaxf(fmaxf(m1, a.x), fmaxf(a.y, a.z)), a.w);
        m2 = fmaxf(fmaxf(fmaxf(m2, b.x), fmaxf(b.y, b.z)), b.w);
    }
    for (int o = 16; o; o >>= 1) {
        m1 = fmaxf(m1, __shfl_xor_sync(0xffffffffu, m1, o));
        m2 = fmaxf(m2, __shfl_xor_sync(0xffffffffu, m2, o));
    }
    __shared__ float shm1[8], shm2[8];
    if ((tid & 31) == 0) { shm1[tid >> 5] = m1; shm2[tid >> 5] = m2; }
    __syncthreads();
    float M1 = shm1[0], M2 = shm2[0];
    for (int w = 1; w < 8; w++) { M1 = fmaxf(M1, shm1[w]); M2 = fmaxf(M2, shm2[w]); }

    float l1 = 0.f, l2 = 0.f, sw = 0.f, s1w = 0.f, s2w = 0.f, cnt = 0.f;
    for (int v = tid; v < NV; v += 256) {
        float4 a = s1r[v], b = s2r[v];
        l1 += __expf(a.x - M1) + __expf(a.y - M1) + __expf(a.z - M1) + __expf(a.w - M1);
        l2 += __expf(b.x - M2) + __expf(b.y - M2) + __expf(b.z - M2) + __expf(b.w - M2);
        int4 q = ql4[v];
        if (q.x == lbl || q.y == lbl || q.z == lbl || q.w == lbl) {
            const float va[4] = {a.x, a.y, a.z, a.w};
            const float vb[4] = {b.x, b.y, b.z, b.w};
            const int   qq[4] = {q.x, q.y, q.z, q.w};
#pragma unroll
            for (int e = 0; e < 4; e++) {
                if (qq[e] != lbl) continue;
                int jj = j0 + v * 4 + e;
                int r = (jj - hdr) & (NQ - 1);
                const float* frow = (r < NROW) ? (old_embeds + (size_t)r * DDIM)
                                               : (feat_queue + (size_t)jj * DDIM);
                float dot = 0.f;
#pragma unroll 8
                for (int d = 0; d < DDIM; d++) dot = fmaf(oei[d], frow[d], dot);
                float w = 0.5f * (dot + 1.0f);
                sw += w; s1w += w * va[e]; s2w += w * vb[e]; cnt += 1.f;
            }
        }
    }
    for (int o = 16; o; o >>= 1) {
        l1  += __shfl_down_sync(0xffffffffu, l1, o);
        l2  += __shfl_down_sync(0xffffffffu, l2, o);
        sw  += __shfl_down_sync(0xffffffffu, sw, o);
        s1w += __shfl_down_sync(0xffffffffu, s1w, o);
        s2w += __shfl_down_sync(0xffffffffu, s2w, o);
        cnt += __shfl_down_sync(0xffffffffu, cnt, o);
    }
    __shared__ float shl1[8], shl2[8], shsw[8], shs1[8], shs2[8], shc[8];
    if ((tid & 31) == 0) {
        int w = tid >> 5;
        shl1[w] = l1; shl2[w] = l2; shsw[w] = sw; shs1[w] = s1w; shs2[w] = s2w; shc[w] = cnt;
    }
    __syncthreads();
    if (tid == 0) {
        float L1 = 0, L2 = 0, SW = 0, S1 = 0, S2 = 0, CN = 0;
        for (int w = 0; w < 8; w++) {
            L1 += shl1[w]; L2 += shl2[w]; SW += shsw[w];
            S1 += shs1[w]; S2 += shs2[w]; CN += shc[w];
        }
        float* p = g_part + blockIdx.x * 8;
        p[0] = M1; p[1] = L1; p[2] = M2; p[3] = L2;
        p[4] = SW; p[5] = S1; p[6] = S2; p[7] = CN;
    }
}

// ---------------- finalize ----------------
__global__ void finalize(float* __restrict__ out) {
    int tid = threadIdx.x;   // 128 threads, one row each
    const float* pa = g_part + (2 * tid) * 8;
    const float* pb = g_part + (2 * tid + 1) * 8;
    float M1 = fmaxf(pa[0], pb[0]);
    float L1 = pa[1] * __expf(pa[0] - M1) + pb[1] * __expf(pb[0] - M1);
    float M2 = fmaxf(pa[2], pb[2]);
    float L2 = pa[3] * __expf(pa[2] - M2) + pb[3] * __expf(pb[2] - M2);
    float SW = pa[4] + pb[4];
    float S1 = pa[5] + pb[5];
    float S2 = pa[6] + pb[6];
    float CN = pa[7] + pb[7];
    float lse1 = M1 + logf(L1);
    float lse2 = M2 + logf(L2);
    float ic = 1.0f / CN;
    float t1 = (S1 - lse1 * SW) * ic;
    float t2 = (S2 - lse2 * SW) * ic;
    for (int o = 16; o; o >>= 1) {
        t1 += __shfl_down_sync(0xffffffffu, t1, o);
        t2 += __shfl_down_sync(0xffffffffu, t2, o);
    }
    __shared__ float sh1[4], sh2[4];
    if ((tid & 31) == 0) { sh1[tid >> 5] = t1; sh2[tid >> 5] = t2; }
    __syncthreads();
    if (tid == 0) {
        out[0] = -(sh1[0] + sh1[1] + sh1[2] + sh1[3]) / (float)NROW;
        out[1] = -(sh2[0] + sh2[1] + sh2[2] + sh2[3]) / (float)NROW;
    }
}

// ---------------- launch ----------------
extern "C" void kernel_launch(void* const* d_in, const int* in_sizes, int n_in,
                              void* d_out, int out_size) {
    const float* old_embeds   = (const float*)d_in[0];
    const float* old_logits   = (const float*)d_in[1];
    const float* new_embeds   = (const float*)d_in[2];
    const float* new_logits   = (const float*)d_in[3];
    const int*   labels       = (const int*)d_in[4];
    const float* feat_queue   = (const float*)d_in[5];
    const float* logit_queue  = (const float*)d_in[6];
    const int*   queue_labels = (const int*)d_in[7];
    const int*   header       = (const int*)d_in[8];
    float* out = (float*)d_out;

    unsigned short *p_a1, *p_a2;
    float *p_s1, *p_s2;
    cudaGetSymbolAddress((void**)&p_a1, g_a1);
    cudaGetSymbolAddress((void**)&p_a2, g_a2);
    cudaGetSymbolAddress((void**)&p_s1, g_s1);
    cudaGetSymbolAddress((void**)&p_s2, g_s2);

    cudaFuncSetAttribute(gemm_mma, cudaFuncAttributeMaxDynamicSharedMemorySize, GEMM_SMEM);

    normalize_half<<<NROW, 128>>>(new_embeds);
    half_logits<<<(NROW * CDIM) / (256 * 4), 256>>>(new_logits);
    build_qlab<<<NQ / 256, 256>>>(queue_labels, labels, header);

    gemm_mma<<<NQ / 128, 256, GEMM_SMEM>>>(p_a1, feat_queue, old_embeds,
                                           header, p_s1, DDIM);
    gemm_mma<<<NQ / 128, 256, GEMM_SMEM>>>(p_a2, logit_queue, old_logits,
                                           header, p_s2, CDIM);

    row_reduce<<<2 * NROW, 256>>>(old_embeds, feat_queue, labels, header);
    finalize<<<1, 128>>>(out);
}

// round 11
// speedup vs baseline: 1.4727x; 1.2240x over previous
#include <cuda_runtime.h>
#include <cuda_fp16.h>
#include <cstdint>
#include <math.h>

// Shapes (fixed)
constexpr int NROW = 128;
constexpr int DDIM = 512;
constexpr int CDIM = 8192;
constexpr int NQ   = 32768;

// ---------------- device scratch ----------------
__device__ __align__(16) float g_s1[(size_t)NROW * NQ];
__device__ __align__(16) float g_s2[(size_t)NROW * NQ];
__device__ __align__(16) unsigned short g_a1[NROW * DDIM];   // fp16 normalized new_embeds
__device__ __align__(16) unsigned short g_a2[NROW * CDIM];   // fp16 new_logits
__device__ int   g_qlab[NQ];
__device__ float g_part[256 * 8];     // per (row, half): m1,l1,m2,l2,sw,s1w,s2w,cnt

// ---------------- small helpers ----------------
__device__ __forceinline__ uint32_t smem_u32(const void* p) {
    uint32_t a;
    asm("{ .reg .u64 t; cvta.to.shared.u64 t, %1; cvt.u32.u64 %0, t; }" : "=r"(a) : "l"(p));
    return a;
}
__device__ __forceinline__ void ldm4(uint32_t* r, uint32_t addr) {
    asm volatile("ldmatrix.sync.aligned.m8n8.x4.shared.b16 {%0,%1,%2,%3}, [%4];"
                 : "=r"(r[0]), "=r"(r[1]), "=r"(r[2]), "=r"(r[3]) : "r"(addr));
}
__device__ __forceinline__ void mma_f16(float* d, const uint32_t* a, const uint32_t* b) {
    asm volatile(
        "mma.sync.aligned.m16n8k16.row.col.f32.f16.f16.f32 "
        "{%0,%1,%2,%3}, {%4,%5,%6,%7}, {%8,%9}, {%0,%1,%2,%3};"
        : "+f"(d[0]), "+f"(d[1]), "+f"(d[2]), "+f"(d[3])
        : "r"(a[0]), "r"(a[1]), "r"(a[2]), "r"(a[3]), "r"(b[0]), "r"(b[1]));
}
#define CP16(saddr, gptr) \
    asm volatile("cp.async.ca.shared.global [%0], [%1], 16;" :: "r"(saddr), "l"(gptr))
#define CP_COMMIT() asm volatile("cp.async.commit_group;" ::: "memory")
#define CP_WAIT0()  asm volatile("cp.async.wait_group 0;" ::: "memory")

// ---------------- kernel: normalize new_embeds -> fp16 ----------------
__global__ void normalize_half(const float* __restrict__ x) {
    int i = blockIdx.x, tid = threadIdx.x;           // 128 threads
    const float* xr = x + (size_t)i * DDIM;
    float s = 0.f;
    for (int d = tid; d < DDIM; d += 128) { float v = xr[d]; s += v * v; }
    for (int o = 16; o; o >>= 1) s += __shfl_down_sync(0xffffffffu, s, o);
    __shared__ float sh[4];
    if ((tid & 31) == 0) sh[tid >> 5] = s;
    __syncthreads();
    __shared__ float invs;
    if (tid == 0) invs = 1.0f / fmaxf(sqrtf(sh[0] + sh[1] + sh[2] + sh[3]), 1e-12f);
    __syncthreads();
    float iv = invs;
    for (int d = tid; d < DDIM; d += 128)
        g_a1[i * DDIM + d] = __half_as_ushort(__float2half_rn(xr[d] * iv));
}

// ---------------- kernel: new_logits -> fp16 ----------------
__global__ void half_logits(const float* __restrict__ x) {
    int idx = (blockIdx.x * blockDim.x + threadIdx.x) * 4;   // over 128*8192
    float4 v = *(const float4*)(x + idx);
    __half2 h0 = __floats2half2_rn(v.x, v.y);
    __half2 h1 = __floats2half2_rn(v.z, v.w);
    uint2 p; p.x = *(uint32_t*)&h0; p.y = *(uint32_t*)&h1;
    *(uint2*)(g_a2 + idx) = p;
}

// ---------------- kernel: updated queue labels ----------------
__global__ void build_qlab(const int* __restrict__ ql, const int* __restrict__ labels,
                           const int* __restrict__ hdrp) {
    int j = blockIdx.x * blockDim.x + threadIdx.x;
    int hdr = *hdrp;
    int r = (j - hdr) & (NQ - 1);
    g_qlab[j] = (r < NROW) ? labels[r] : ql[j];
}

// ---------------- fused fp16 GEMMs, cp.async-staged B, 1 barrier/chunk ----------------
// blocks [0,256): out2 = A2 @ B2^T (K=CDIM);  blocks [256,512): out1 = A1 @ B1^T (K=DDIM)
// CTA tile 128x128, BK=32; 8 warps (4M x 2N), warp tile 32x64.
// Per iter c: wait0+sync -> issue cp.async {Bf32(c+2)->stage(c&1), A(c+1)->Atile((c+1)&1)}
//             -> convert B(c+1): stage((c+1)&1) -> Bfp16((c+1)&1) -> compute(c).
constexpr int BPAD = 80;                 // fp16 tile row stride (conflict-free ldmatrix)
constexpr int FSTR = 144;                // fp32 staging row stride (128B data + 16B pad)
constexpr int SZ_T = 128 * BPAD;         // 10240
constexpr int SZ_F = 128 * FSTR;         // 18432
constexpr int O_A   = 0;                 // [2 stages x 10240]
constexpr int O_B16 = 2 * SZ_T;          // 20480 [2 stages x 10240]
constexpr int O_FS  = 4 * SZ_T;          // 40960 [2 stages x 18432]
constexpr int GEMM_SMEM = O_FS + 2 * SZ_F;   // 77824 -> 2 CTAs/SM

__global__ __launch_bounds__(256, 2) void gemm_mma(
    const unsigned short* __restrict__ A2, const float* __restrict__ Bq2,
    const float* __restrict__ Bold2, float* __restrict__ out2, int K2,
    const unsigned short* __restrict__ A1, const float* __restrict__ Bq1,
    const float* __restrict__ Bold1, float* __restrict__ out1, int K1,
    const int* __restrict__ hdrp)
{
    extern __shared__ char smem[];
    const uint32_t sb = smem_u32(smem);
    const int tid = threadIdx.x, lane = tid & 31, wid = tid >> 5;
    const int wm = wid >> 1, wn = wid & 1;

    // select problem
    const bool is2 = (blockIdx.x < 256);
    const int n0 = (is2 ? blockIdx.x : blockIdx.x - 256) * 128;
    const int K  = is2 ? K2 : K1;
    const unsigned short* A = is2 ? A2 : A1;
    const float* Bq   = is2 ? Bq2 : Bq1;
    const float* Bold = is2 ? Bold2 : Bold1;
    float* out = is2 ? out2 : out1;
    const int nch = K >> 5;

    // B gmem row with circular-queue redirect; 2 threads per row, 64B (16 fp32) each
    const int rb = tid >> 1, seg = tid & 1;
    const int hdr = *hdrp;
    const int j = n0 + rb;
    const int r = (j - hdr) & (NQ - 1);
    const char* gB = (const char*)(((r < NROW) ? (Bold + (size_t)r * K)
                                               : (Bq + (size_t)j * K)) + seg * 16);

    // A: 2 threads per row, 32B each (row = 64B fp16 per chunk)
    const int arow = tid >> 1;
    const int acol = (tid & 1) * 32;
    const char* gA = (const char*)A + (size_t)arow * K * 2 + acol;
    const uint32_t sA = sb + O_A + arow * BPAD + acol;

    // ldmatrix lane addressing
    const int g = lane >> 3, lr = lane & 7;
    const uint32_t aRowOff = (uint32_t)(wm * 32 + (g & 1) * 8 + lr) * BPAD + (g >> 1) * 16;
    const uint32_t bRowOff = (uint32_t)(wn * 64 + (g >> 1) * 8 + lr) * BPAD + (g & 1) * 16;

    float acc[2][8][4];
#pragma unroll
    for (int mt = 0; mt < 2; mt++)
#pragma unroll
        for (int nt = 0; nt < 8; nt++)
#pragma unroll
            for (int u = 0; u < 4; u++) acc[mt][nt][u] = 0.f;

    auto cpA = [&](int c, int st) {
        const char* s0 = gA + (size_t)c * 64;
        uint32_t d0 = sA + st * SZ_T;
        CP16(d0, s0); CP16(d0 + 16, s0 + 16);
    };
    auto cpB = [&](int c, int st) {
        const char* s0 = gB + (size_t)c * 128;
        uint32_t d0 = sb + O_FS + st * SZ_F + rb * FSTR + seg * 64;
#pragma unroll
        for (int i = 0; i < 4; i++) CP16(d0 + 16 * i, s0 + 16 * i);
    };
    // convert chunk held in stage st2: fp32 staging -> fp16 tile
    auto convertB = [&](int st2) {
        const char* src = smem + O_FS + st2 * SZ_F + rb * FSTR + seg * 64;
        float4 f0 = *(const float4*)(src);
        float4 f1 = *(const float4*)(src + 16);
        float4 f2 = *(const float4*)(src + 32);
        float4 f3 = *(const float4*)(src + 48);
        __half2 h0 = __floats2half2_rn(f0.x, f0.y);
        __half2 h1 = __floats2half2_rn(f0.z, f0.w);
        __half2 h2 = __floats2half2_rn(f1.x, f1.y);
        __half2 h3 = __floats2half2_rn(f1.z, f1.w);
        __half2 h4 = __floats2half2_rn(f2.x, f2.y);
        __half2 h5 = __floats2half2_rn(f2.z, f2.w);
        __half2 h6 = __floats2half2_rn(f3.x, f3.y);
        __half2 h7 = __floats2half2_rn(f3.z, f3.w);
        uint4 p0, p1;
        p0.x = *(uint32_t*)&h0; p0.y = *(uint32_t*)&h1;
        p0.z = *(uint32_t*)&h2; p0.w = *(uint32_t*)&h3;
        p1.x = *(uint32_t*)&h4; p1.y = *(uint32_t*)&h5;
        p1.z = *(uint32_t*)&h6; p1.w = *(uint32_t*)&h7;
        char* d = smem + O_B16 + st2 * SZ_T + rb * BPAD + seg * 32;
        *(uint4*)d = p0;
        *(uint4*)(d + 16) = p1;
    };
    auto compute = [&](int st) {
        const uint32_t bA = sb + O_A + st * SZ_T + aRowOff;
        const uint32_t bB = sb + O_B16 + st * SZ_T + bRowOff;
#pragma unroll
        for (int ks = 0; ks < 2; ks++) {
            uint32_t a[2][4], b[4][4];
            ldm4(a[0], bA + ks * 32);
            ldm4(a[1], bA + 16 * BPAD + ks * 32);
#pragma unroll
            for (int p = 0; p < 4; p++) ldm4(b[p], bB + p * 16 * BPAD + ks * 32);
#pragma unroll
            for (int mt = 0; mt < 2; mt++)
#pragma unroll
                for (int nt = 0; nt < 8; nt++)
                    mma_f16(acc[mt][nt], a[mt], &b[nt >> 1][(nt & 1) * 2]);
        }
    };

    // ---- prologue: land B(0), B(1), A(0); convert B(0) ----
    cpB(0, 0);
    cpB(1, 1);
    cpA(0, 0);
    CP_COMMIT();
    CP_WAIT0();
    __syncthreads();
    convertB(0);
    __syncthreads();

    // ---- main loop: one barrier + one wait per chunk ----
    for (int c = 0; c < nch; c++) {
        const int st = c & 1;
        if (c > 0) { CP_WAIT0(); __syncthreads(); }
        if (c + 2 < nch) cpB(c + 2, st);          // stage(st): old B(c) consumed last iter
        if (c + 1 < nch) cpA(c + 1, st ^ 1);
        CP_COMMIT();                               // always (empty group ok)
        if (c + 1 < nch) convertB(st ^ 1);         // B(c+1): landed (waited at iter top)
        compute(st);
    }

    // ---- epilogue ----
    const int qr = lane >> 2, qc = (lane & 3) * 2;
#pragma unroll
    for (int mt = 0; mt < 2; mt++) {
        const int row = wm * 32 + mt * 16 + qr;
#pragma unroll
        for (int nt = 0; nt < 8; nt++) {
            const int col = n0 + wn * 64 + nt * 8 + qc;
            float2 v0; v0.x = acc[mt][nt][0]; v0.y = acc[mt][nt][1];
            float2 v1; v1.x = acc[mt][nt][2]; v1.y = acc[mt][nt][3];
            *(float2*)(out + (size_t)row * NQ + col) = v0;
            *(float2*)(out + (size_t)(row + 8) * NQ + col) = v1;
        }
    }
}

// ---------------- per-row reduction: 2 blocks per row (half-Q each) ----------------
__global__ __launch_bounds__(256) void row_reduce(
    const float* __restrict__ old_embeds, const float* __restrict__ feat_queue,
    const int* __restrict__ labels, const int* __restrict__ hdrp)
{
    const int i = blockIdx.x >> 1, half = blockIdx.x & 1, tid = threadIdx.x;
    const int lbl = labels[i];
    const int hdr = *hdrp;
    const int j0 = half * (NQ / 2);
    const float4* s1r = (const float4*)(g_s1 + (size_t)i * NQ + j0);
    const float4* s2r = (const float4*)(g_s2 + (size_t)i * NQ + j0);
    const int4*   ql4 = (const int4*)(g_qlab + j0);
    const float* oei = old_embeds + (size_t)i * DDIM;
    constexpr int NV = (NQ / 2) / 4;

    float m1 = -INFINITY, m2 = -INFINITY;
    for (int v = tid; v < NV; v += 256) {
        float4 a = s1r[v], b = s2r[v];
        m1 = fmaxf(fmaxf(fmaxf(m1, a.x), fmaxf(a.y, a.z)), a.w);
        m2 = fmaxf(fmaxf(fmaxf(m2, b.x), fmaxf(b.y, b.z)), b.w);
    }
    for (int o = 16; o; o >>= 1) {
        m1 = fmaxf(m1, __shfl_xor_sync(0xffffffffu, m1, o));
        m2 = fmaxf(m2, __shfl_xor_sync(0xffffffffu, m2, o));
    }
    __shared__ float shm1[8], shm2[8];
    if ((tid & 31) == 0) { shm1[tid >> 5] = m1; shm2[tid >> 5] = m2; }
    __syncthreads();
    float M1 = shm1[0], M2 = shm2[0];
    for (int w = 1; w < 8; w++) { M1 = fmaxf(M1, shm1[w]); M2 = fmaxf(M2, shm2[w]); }

    float l1 = 0.f, l2 = 0.f, sw = 0.f, s1w = 0.f, s2w = 0.f, cnt = 0.f;
    for (int v = tid; v < NV; v += 256) {
        float4 a = s1r[v], b = s2r[v];
        l1 += __expf(a.x - M1) + __expf(a.y - M1) + __expf(a.z - M1) + __expf(a.w - M1);
        l2 += __expf(b.x - M2) + __expf(b.y - M2) + __expf(b.z - M2) + __expf(b.w - M2);
        int4 q = ql4[v];
        if (q.x == lbl || q.y == lbl || q.z == lbl || q.w == lbl) {
            const float va[4] = {a.x, a.y, a.z, a.w};
            const float vb[4] = {b.x, b.y, b.z, b.w};
            const int   qq[4] = {q.x, q.y, q.z, q.w};
#pragma unroll
            for (int e = 0; e < 4; e++) {
                if (qq[e] != lbl) continue;
                int jj = j0 + v * 4 + e;
                int r = (jj - hdr) & (NQ - 1);
                const float* frow = (r < NROW) ? (old_embeds + (size_t)r * DDIM)
                                               : (feat_queue + (size_t)jj * DDIM);
                float dot = 0.f;
#pragma unroll 8
                for (int d = 0; d < DDIM; d++) dot = fmaf(oei[d], frow[d], dot);
                float w = 0.5f * (dot + 1.0f);
                sw += w; s1w += w * va[e]; s2w += w * vb[e]; cnt += 1.f;
            }
        }
    }
    for (int o = 16; o; o >>= 1) {
        l1  += __shfl_down_sync(0xffffffffu, l1, o);
        l2  += __shfl_down_sync(0xffffffffu, l2, o);
        sw  += __shfl_down_sync(0xffffffffu, sw, o);
        s1w += __shfl_down_sync(0xffffffffu, s1w, o);
        s2w += __shfl_down_sync(0xffffffffu, s2w, o);
        cnt += __shfl_down_sync(0xffffffffu, cnt, o);
    }
    __shared__ float shl1[8], shl2[8], shsw[8], shs1[8], shs2[8], shc[8];
    if ((tid & 31) == 0) {
        int w = tid >> 5;
        shl1[w] = l1; shl2[w] = l2; shsw[w] = sw; shs1[w] = s1w; shs2[w] = s2w; shc[w] = cnt;
    }
    __syncthreads();
    if (tid == 0) {
        float L1 = 0, L2 = 0, SW = 0, S1 = 0, S2 = 0, CN = 0;
        for (int w = 0; w < 8; w++) {
            L1 += shl1[w]; L2 += shl2[w]; SW += shsw[w];
            S1 += shs1[w]; S2 += shs2[w]; CN += shc[w];
        }
        float* p = g_part + blockIdx.x * 8;
        p[0] = M1; p[1] = L1; p[2] = M2; p[3] = L2;
        p[4] = SW; p[5] = S1; p[6] = S2; p[7] = CN;
    }
}

// ---------------- finalize ----------------
__global__ void finalize(float* __restrict__ out) {
    int tid = threadIdx.x;   // 128 threads, one row each
    const float* pa = g_part + (2 * tid) * 8;
    const float* pb = g_part + (2 * tid + 1) * 8;
    float M1 = fmaxf(pa[0], pb[0]);
    float L1 = pa[1] * __expf(pa[0] - M1) + pb[1] * __expf(pb[0] - M1);
    float M2 = fmaxf(pa[2], pb[2]);
    float L2 = pa[3] * __expf(pa[2] - M2) + pb[3] * __expf(pb[2] - M2);
    float SW = pa[4] + pb[4];
    float S1 = pa[5] + pb[5];
    float S2 = pa[6] + pb[6];
    float CN = pa[7] + pb[7];
    float lse1 = M1 + logf(L1);
    float lse2 = M2 + logf(L2);
    float ic = 1.0f / CN;
    float t1 = (S1 - lse1 * SW) * ic;
    float t2 = (S2 - lse2 * SW) * ic;
    for (int o = 16; o; o >>= 1) {
        t1 += __shfl_down_sync(0xffffffffu, t1, o);
        t2 += __shfl_down_sync(0xffffffffu, t2, o);
    }
    __shared__ float sh1[4], sh2[4];
    if ((tid & 31) == 0) { sh1[tid >> 5] = t1; sh2[tid >> 5] = t2; }
    __syncthreads();
    if (tid == 0) {
        out[0] = -(sh1[0] + sh1[1] + sh1[2] + sh1[3]) / (float)NROW;
        out[1] = -(sh2[0] + sh2[1] + sh2[2] + sh2[3]) / (float)NROW;
    }
}

// ---------------- launch ----------------
extern "C" void kernel_launch(void* const* d_in, const int* in_sizes, int n_in,
                              void* d_out, int out_size) {
    const float* old_embeds   = (const float*)d_in[0];
    const float* old_logits   = (const float*)d_in[1];
    const float* new_embeds   = (const float*)d_in[2];
    const float* new_logits   = (const float*)d_in[3];
    const int*   labels       = (const int*)d_in[4];
    const float* feat_queue   = (const float*)d_in[5];
    const float* logit_queue  = (const float*)d_in[6];
    const int*   queue_labels = (const int*)d_in[7];
    const int*   header       = (const int*)d_in[8];
    float* out = (float*)d_out;

    unsigned short *p_a1, *p_a2;
    float *p_s1, *p_s2;
    cudaGetSymbolAddress((void**)&p_a1, g_a1);
    cudaGetSymbolAddress((void**)&p_a2, g_a2);
    cudaGetSymbolAddress((void**)&p_s1, g_s1);
    cudaGetSymbolAddress((void**)&p_s2, g_s2);

    cudaFuncSetAttribute(gemm_mma, cudaFuncAttributeMaxDynamicSharedMemorySize, GEMM_SMEM);

    normalize_half<<<NROW, 128>>>(new_embeds);
    half_logits<<<(NROW * CDIM) / (256 * 4), 256>>>(new_logits);
    build_qlab<<<NQ / 256, 256>>>(queue_labels, labels, header);

    // fused: blocks [0,256) -> l2 GEMM (K=CDIM), blocks [256,512) -> l1 GEMM (K=DDIM)
    gemm_mma<<<512, 256, GEMM_SMEM>>>(p_a2, logit_queue, old_logits, p_s2, CDIM,
                                      p_a1, feat_queue, old_embeds, p_s1, DDIM,
                                      header);

    row_reduce<<<2 * NROW, 256>>>(old_embeds, feat_queue, labels, header);
    finalize<<<1, 128>>>(out);
}